// round 12
// baseline (speedup 1.0000x reference)
#include <cuda_runtime.h>
#include <math.h>

#define NN   20000
#define DD   128
#define EE   60000
#define PERL 4000
#define NB   20
#define NBLK 144
#define NTHR 256

// ---------------- device scratch ----------------
__device__ float g_aggs[NN * DD];
__device__ float g_aggf[NN * DD];
__device__ float g_Ws1t[5 * DD * DD];
__device__ float g_Ws2t[5 * DD * DD];
__device__ float g_Wf1t[4 * 2 * DD * DD];
__device__ float g_Wf2t[4 * DD * DD];
__device__ float g_Wnf1t[DD * DD];
__device__ float g_Wnf2t[DD * DD];
__device__ float g_Gswih_t[5 * 3 * DD * DD];
__device__ float g_Gfwih_t[5 * 3 * DD * DD];
__device__ int g_esrc[EE];
__device__ int g_edst[EE];
__device__ int g_ecnt[NB];
__device__ int g_eoff[NB + 1];
__device__ int g_ecur[NB];
__device__ int g_nodes[NN];
__device__ int g_ncnt[NB];
__device__ int g_noff[NB + 1];
__device__ int g_ncur[NB];
__device__ volatile unsigned g_phase;
__device__ unsigned g_barcnt;

__device__ __forceinline__ int code2t(int c) {
    switch (c) {
        case 1: return 3;
        case 2: return 1;
        case 3: return 0;
        case 4: return 4;
        default: return 2;
    }
}
__device__ __forceinline__ float sigmoidf_(float x) { return 1.f / (1.f + expf(-x)); }
__device__ __forceinline__ void fma2(unsigned long long& d, unsigned long long a,
                                     unsigned long long b) {
    asm("fma.rn.f32x2 %0, %1, %2, %0;" : "+l"(d) : "l"(a), "l"(b));
}
__device__ __forceinline__ float unpack_sum(unsigned long long a) {
    float lo, hi;
    asm("mov.b64 {%0, %1}, %2;" : "=f"(lo), "=f"(hi) : "l"(a));
    return lo + hi;
}

// software grid barrier: all NBLK blocks resident (1 block/SM by smem).
__device__ __forceinline__ void gbar(unsigned tgt) {
    __syncthreads();
    if (threadIdx.x == 0) {
        __threadfence();
        if (atomicAdd(&g_barcnt, 1u) == NBLK - 1) {
            g_barcnt = 0;
            __threadfence();
            atomicAdd((unsigned*)&g_phase, 1u);
        } else {
            while ((int)(*(volatile unsigned*)&g_phase - tgt) < 0) {}
            __threadfence();
        }
    }
    __syncthreads();
}

__device__ __forceinline__ void tr1(const float* __restrict__ src, float* __restrict__ dst,
                                    int idx, int K, int J) {
    int m = idx / (K * J);
    int r = idx - m * (K * J);
    int k = r / J;
    int j = r - k * J;
    dst[m * K * J + j * K + k] = src[idx];
}

// stage transposed weights into smem with vec-lane row permutation + XOR swizzle.
__device__ __forceinline__ void stage_w_vec(float* __restrict__ dst,
                                            const float* __restrict__ src,
                                            int nblk, int k4n, int tid, int nthr) {
    float4* d = (float4*)dst;
    const float4* sp = (const float4*)src;
    int tot = nblk * 128 * k4n;
    for (int i = tid; i < tot; i += nthr) {
        int r = i / k4n;
        int c = i - r * k4n;
        int gb = r >> 7, rr = r & 127;
        int lane = rr & 31, oi = rr >> 5;
        int srow = (gb << 7) + lane * 4 + oi;
        d[r * k4n + (c ^ (r & 7))] = sp[srow * k4n + c];
    }
}
__device__ __forceinline__ void stage_w_f1(float* __restrict__ dst,
                                           const float* __restrict__ src,
                                           int tid, int nthr) {
    float4* d = (float4*)dst;
    const float4* sp = (const float4*)src;
    for (int i = tid; i < 8192; i += nthr) {
        int h = i >> 12;
        int r = (i >> 5) & 127;
        int c = i & 31;
        int lane = r & 31, oi = r >> 5;
        int srow = lane * 4 + oi;
        d[h * 4096 + r * 32 + (c ^ (r & 7))] = sp[srow * 64 + h * 32 + c];
    }
}

template <int G, int NOUT, int K4N, int XS4, bool ZERO, int UNR>
__device__ __forceinline__ void gemm_p(const float* __restrict__ sW,
                                       const float* __restrict__ sX, int lane,
                                       unsigned long long (&acc)[G][NOUT]) {
    const ulonglong2* wU = (const ulonglong2*)sW;
    const ulonglong2* xU = (const ulonglong2*)sX;
    int s = lane & 7;
    if (ZERO) {
#pragma unroll
        for (int g = 0; g < G; g++)
#pragma unroll
            for (int oi = 0; oi < NOUT; oi++) acc[g][oi] = 0ull;
    }
#pragma unroll UNR
    for (int k4 = 0; k4 < K4N; k4++) {
        int kk = k4 ^ s;
        ulonglong2 xv[G];
#pragma unroll
        for (int g = 0; g < G; g++) xv[g] = xU[g * XS4 + k4];
#pragma unroll
        for (int oi = 0; oi < NOUT; oi++) {
            ulonglong2 wv = wU[(oi * 32 + lane) * K4N + kk];
#pragma unroll
            for (int g = 0; g < G; g++) {
                fma2(acc[g][oi], xv[g].x, wv.x);
                fma2(acc[g][oi], xv[g].y, wv.y);
            }
        }
    }
}

// GRU GEMM with literal unroll 8 (R7 codegen)
template <int G, int NOUT>
__device__ __forceinline__ void gemm_g(const float* __restrict__ sW,
                                       const float* __restrict__ sX, int lane,
                                       unsigned long long (&acc)[G][NOUT]) {
    const ulonglong2* wU = (const ulonglong2*)sW;
    const ulonglong2* xU = (const ulonglong2*)sX;
    int s = lane & 7;
#pragma unroll
    for (int g = 0; g < G; g++)
#pragma unroll
        for (int oi = 0; oi < NOUT; oi++) acc[g][oi] = 0ull;
#pragma unroll 8
    for (int k4 = 0; k4 < 32; k4++) {
        int kk = k4 ^ s;
        ulonglong2 xv[G];
#pragma unroll
        for (int g = 0; g < G; g++) xv[g] = xU[g * 32 + k4];
#pragma unroll
        for (int oi = 0; oi < NOUT; oi++) {
            ulonglong2 wv = wU[(oi * 32 + lane) * 32 + kk];
#pragma unroll
            for (int g = 0; g < G; g++) {
                fma2(acc[g][oi], xv[g].x, wv.x);
                fma2(acc[g][oi], xv[g].y, wv.y);
            }
        }
    }
}

#define INIT_TOTAL (NN * DD)
#define PREP_TOTAL 884736

// ================= the single persistent kernel =================
__global__ void __launch_bounds__(256, 1)
k_all(const float* __restrict__ hs_init, const int* __restrict__ gate,
      const float* __restrict__ Ws1, const float* __restrict__ bs1,
      const float* __restrict__ Ws2, const float* __restrict__ bs2,
      const float* __restrict__ Wf1, const float* __restrict__ bf1,
      const float* __restrict__ Wf2, const float* __restrict__ bf2,
      const float* __restrict__ Wnf1, const float* __restrict__ bnf1,
      const float* __restrict__ Wnf2, const float* __restrict__ bnf2,
      const float* __restrict__ Gs, const float* __restrict__ Gs_bih,
      const float* __restrict__ Gs_bhh,
      const float* __restrict__ Gf, const float* __restrict__ Gf_bih,
      const float* __restrict__ Gf_bhh,
      const int* __restrict__ ei, const int* __restrict__ flev,
      float* __restrict__ hs, float* __restrict__ hf) {
    extern __shared__ float sm[];
    __shared__ int se_cnt[NB], se_base[NB], se_cur[NB];
    __shared__ int sn_cnt[NB], sn_base[NB], sn_cur[NB];

    int bid = blockIdx.x, tid = threadIdx.x;
    int w = tid >> 5, lane = tid & 31;
    unsigned tgt = *(volatile unsigned*)&g_phase;
    const int stride = NBLK * NTHR;
    int t0 = bid * NTHR + tid;

    // ---------- phase 0: count + init + weight transposes ----------
    for (int i = t0; i < EE; i += stride) {
        int dst = ei[EE + i];
        atomicAdd(&g_ecnt[(flev[dst] - 1) * 5 + code2t(gate[dst])], 1);
    }
    for (int i = t0; i < NN - PERL; i += stride) {
        int v = i + PERL;
        atomicAdd(&g_ncnt[(flev[v] - 1) * 5 + code2t(gate[v])], 1);
    }
    for (int i = t0; i < INIT_TOTAL; i += stride) {
        int v = i >> 7;
        hs[i] = (gate[v] == 0) ? hs_init[i] : 0.f;
        hf[i] = 0.f;
        g_aggs[i] = 0.f;
        g_aggf[i] = 0.f;
    }
    for (int i = t0; i < PREP_TOTAL; i += stride) {
        int idx = i;
        if (idx < 81920) { tr1(Ws1, g_Ws1t, idx, 128, 128); continue; }
        idx -= 81920;
        if (idx < 81920) { tr1(Ws2, g_Ws2t, idx, 128, 128); continue; }
        idx -= 81920;
        if (idx < 131072) { tr1(Wf1, g_Wf1t, idx, 256, 128); continue; }
        idx -= 131072;
        if (idx < 65536) { tr1(Wf2, g_Wf2t, idx, 128, 128); continue; }
        idx -= 65536;
        if (idx < 16384) { tr1(Wnf1, g_Wnf1t, idx, 128, 128); continue; }
        idx -= 16384;
        if (idx < 16384) { tr1(Wnf2, g_Wnf2t, idx, 128, 128); continue; }
        idx -= 16384;
        if (idx < 245760) { tr1(Gs, g_Gswih_t, idx, 128, 384); continue; }
        idx -= 245760;
        tr1(Gf, g_Gfwih_t, idx, 128, 384);
    }
    gbar(++tgt);

    // ---------- phase 1: scan (block 0) ----------
    if (bid == 0 && tid == 0) {
        int s = 0, t = 0;
        for (int b = 0; b < NB; b++) {
            g_eoff[b] = s; g_ecur[b] = s; s += g_ecnt[b];
            g_noff[b] = t; g_ncur[b] = t; t += g_ncnt[b];
            g_ecnt[b] = 0;
            g_ncnt[b] = 0;
        }
        g_eoff[NB] = s;
        g_noff[NB] = t;
    }
    gbar(++tgt);

    // ---------- phase 2: block-aggregated scatter ----------
    for (int b0 = bid * NTHR; b0 < EE; b0 += stride) {
        int i = b0 + tid;
        if (tid < NB) {
            se_cnt[tid] = 0; sn_cnt[tid] = 0;
            se_cur[tid] = 0; sn_cur[tid] = 0;
        }
        __syncthreads();
        int eb = -1, esrc = 0, edst = 0;
        if (i < EE) {
            esrc = ei[i]; edst = ei[EE + i];
            eb = (flev[edst] - 1) * 5 + code2t(gate[edst]);
            atomicAdd(&se_cnt[eb], 1);
        }
        int nb = -1, v = i + PERL;
        if (i < NN - PERL) {
            nb = (flev[v] - 1) * 5 + code2t(gate[v]);
            atomicAdd(&sn_cnt[nb], 1);
        }
        __syncthreads();
        if (tid < NB) {
            if (se_cnt[tid] > 0) se_base[tid] = atomicAdd(&g_ecur[tid], se_cnt[tid]);
            if (sn_cnt[tid] > 0) sn_base[tid] = atomicAdd(&g_ncur[tid], sn_cnt[tid]);
        }
        __syncthreads();
        if (eb >= 0) {
            int p = se_base[eb] + atomicAdd(&se_cur[eb], 1);
            g_esrc[p] = esrc;
            g_edst[p] = edst;
        }
        if (nb >= 0) {
            int p = sn_base[nb] + atomicAdd(&sn_cur[nb], 1);
            g_nodes[p] = v;
        }
        __syncthreads();
    }
    gbar(++tgt);

    // ---------- phases 3..: levels ----------
    for (int level = 1; level < 5; level++) {
        // ===== edge phase (R11 body) =====
        {
            bool isStruct;
            int t, seg, nseg;
            if (bid < 55) {
                isStruct = true;
                t = bid / 11; seg = bid - t * 11; nseg = 11;
            } else {
                isStruct = false;
                int r = bid - 55;
                if (r < 19)      { t = 0; seg = r;      nseg = 19; }
                else if (r < 32) { t = 1; seg = r - 19; nseg = 13; }
                else if (r < 51) { t = 2; seg = r - 32; nseg = 19; }
                else if (r < 70) { t = 3; seg = r - 51; nseg = 19; }
                else             { t = 4; seg = r - 70; nseg = 19; }
            }
            int b = (level - 1) * 5 + t;
            int eS = g_eoff[b], cnt = g_eoff[b + 1] - eS;
            int nw = nseg * 8;
            int wgi = seg * 8 + w;
            int ws = eS + (int)(((long long)cnt * wgi) / nw);
            int we = eS + (int)(((long long)cnt * (wgi + 1)) / nw);

            if (isStruct) {
                const int G = 12;
                float* sW1 = sm;
                float* sW2 = sm + 16384;
                float* myX = sm + 32768 + w * (G * 128);

                float4 xr[G];
                int dr[G];
                {
                    int nb = we - ws;
#pragma unroll
                    for (int g = 0; g < G; g++) {
                        xr[g] = make_float4(0.f, 0.f, 0.f, 0.f);
                        dr[g] = 0;
                        if (g < nb) {
                            int sn = g_esrc[ws + g];
                            dr[g] = g_edst[ws + g];
                            xr[g] = ((const float4*)(hs + sn * 128))[lane];
                        }
                    }
                }
                stage_w_vec(sW1, g_Ws1t + t * 16384, 1, 32, tid, 256);
                stage_w_vec(sW2, g_Ws2t + t * 16384, 1, 32, tid, 256);
                float4 b1v = ((const float4*)(bs1 + t * 128))[lane];
                float4 b2v = ((const float4*)(bs2 + t * 128))[lane];
                __syncthreads();

                for (int base = ws; base < we; base += G) {
                    int ne = min(G, we - base);
                    int dc[G];
#pragma unroll
                    for (int g = 0; g < G; g++) {
                        ((float4*)(myX + g * 128))[lane] = xr[g];
                        dc[g] = dr[g];
                    }
                    __syncwarp();
                    if (base + G < we) {
                        int nb = we - (base + G);
#pragma unroll
                        for (int g = 0; g < G; g++) {
                            xr[g] = make_float4(0.f, 0.f, 0.f, 0.f);
                            dr[g] = 0;
                            if (g < nb) {
                                int sn = g_esrc[base + G + g];
                                dr[g] = g_edst[base + G + g];
                                xr[g] = ((const float4*)(hs + sn * 128))[lane];
                            }
                        }
                    }
                    unsigned long long a1[G][4];
                    gemm_p<G, 4, 32, 32, true, 2>(sW1, myX, lane, a1);
                    __syncwarp();
#pragma unroll
                    for (int g = 0; g < G; g++) {
                        float4 y = make_float4(fmaxf(unpack_sum(a1[g][0]) + b1v.x, 0.f),
                                               fmaxf(unpack_sum(a1[g][1]) + b1v.y, 0.f),
                                               fmaxf(unpack_sum(a1[g][2]) + b1v.z, 0.f),
                                               fmaxf(unpack_sum(a1[g][3]) + b1v.w, 0.f));
                        ((float4*)(myX + g * 128))[lane] = y;
                    }
                    __syncwarp();
                    unsigned long long a2[G][4];
                    gemm_p<G, 4, 32, 32, true, 2>(sW2, myX, lane, a2);
#pragma unroll
                    for (int g = 0; g < G; g++) {
                        if (g < ne) {
                            float4 v = make_float4(unpack_sum(a2[g][0]) + b2v.x,
                                                   unpack_sum(a2[g][1]) + b2v.y,
                                                   unpack_sum(a2[g][2]) + b2v.z,
                                                   unpack_sum(a2[g][3]) + b2v.w);
                            atomicAdd((float4*)&g_aggs[dc[g] * 128 + lane * 4], v);
                        }
                    }
                    __syncwarp();
                }
            } else {
                const int G = 8;
                float* sW1 = sm;
                float* sW2 = sm + 32768;
                float* myX = sm + 49152 + w * (G * 128);

                bool isnot = (t == 1);
                const float *W2g, *b1g, *b2g;
                if (isnot) {
                    stage_w_vec(sW1, g_Wnf1t, 1, 32, tid, 256);
                    W2g = g_Wnf2t; b1g = bnf1; b2g = bnf2;
                } else {
                    int fi = (t == 0) ? 0 : (t == 2) ? 1 : (t == 3) ? 2 : 3;
                    stage_w_f1(sW1, g_Wf1t + fi * 32768, tid, 256);
                    W2g = g_Wf2t + fi * 16384;
                    b1g = bf1 + fi * 128;
                    b2g = bf2 + fi * 128;
                }
                stage_w_vec(sW2, W2g, 1, 32, tid, 256);

                float4 xa[G], xb[G];
                int dr[G];
                {
                    int nb = we - ws;
#pragma unroll
                    for (int g = 0; g < G; g++) {
                        xa[g] = make_float4(0.f, 0.f, 0.f, 0.f);
                        xb[g] = xa[g];
                        dr[g] = 0;
                        if (g < nb) {
                            int sn = g_esrc[ws + g];
                            dr[g] = g_edst[ws + g];
                            if (isnot) {
                                xa[g] = ((const float4*)(hf + sn * 128))[lane];
                            } else {
                                xa[g] = ((const float4*)(hs + sn * 128))[lane];
                                xb[g] = ((const float4*)(hf + sn * 128))[lane];
                            }
                        }
                    }
                }
                float4 b1v = ((const float4*)b1g)[lane];
                float4 b2v = ((const float4*)b2g)[lane];
                __syncthreads();

                for (int base = ws; base < we; base += G) {
                    int ne = min(G, we - base);
                    int dc[G];
#pragma unroll
                    for (int g = 0; g < G; g++) {
                        ((float4*)(myX + g * 128))[lane] = xa[g];
                        dc[g] = dr[g];
                    }
                    __syncwarp();
                    int nb2 = we - (base + G);
                    if (nb2 > 0) {
#pragma unroll
                        for (int g = 0; g < G; g++) {
                            xa[g] = make_float4(0.f, 0.f, 0.f, 0.f);
                            if (g < nb2) {
                                int sn = g_esrc[base + G + g];
                                xa[g] = ((const float4*)((isnot ? hf : hs) + sn * 128))[lane];
                            }
                        }
                    }
                    unsigned long long a1[G][4];
                    gemm_p<G, 4, 32, 32, true, 4>(sW1, myX, lane, a1);
                    __syncwarp();
                    if (!isnot) {
#pragma unroll
                        for (int g = 0; g < G; g++)
                            ((float4*)(myX + g * 128))[lane] = xb[g];
                        __syncwarp();
                        if (nb2 > 0) {
#pragma unroll
                            for (int g = 0; g < G; g++) {
                                xb[g] = make_float4(0.f, 0.f, 0.f, 0.f);
                                if (g < nb2) {
                                    int sn = g_esrc[base + G + g];
                                    xb[g] = ((const float4*)(hf + sn * 128))[lane];
                                }
                            }
                        }
                        gemm_p<G, 4, 32, 32, false, 4>(sW1 + 16384, myX, lane, a1);
                        __syncwarp();
                    }
                    if (nb2 > 0) {
#pragma unroll
                        for (int g = 0; g < G; g++)
                            dr[g] = (g < nb2) ? g_edst[base + G + g] : 0;
                    }
#pragma unroll
                    for (int g = 0; g < G; g++) {
                        float4 y = make_float4(fmaxf(unpack_sum(a1[g][0]) + b1v.x, 0.f),
                                               fmaxf(unpack_sum(a1[g][1]) + b1v.y, 0.f),
                                               fmaxf(unpack_sum(a1[g][2]) + b1v.z, 0.f),
                                               fmaxf(unpack_sum(a1[g][3]) + b1v.w, 0.f));
                        ((float4*)(myX + g * 128))[lane] = y;
                    }
                    __syncwarp();
                    unsigned long long a2[G][4];
                    gemm_p<G, 4, 32, 32, true, 4>(sW2, myX, lane, a2);
#pragma unroll
                    for (int g = 0; g < G; g++) {
                        if (g < ne) {
                            float4 v = make_float4(unpack_sum(a2[g][0]) + b2v.x,
                                                   unpack_sum(a2[g][1]) + b2v.y,
                                                   unpack_sum(a2[g][2]) + b2v.z,
                                                   unpack_sum(a2[g][3]) + b2v.w);
                            atomicAdd((float4*)&g_aggf[dc[g] * 128 + lane * 4], v);
                        }
                    }
                    __syncwarp();
                }
            }
        }
        gbar(++tgt);

        // ===== GRU phase (blocks 0..139) =====
        if (bid < 140) {
            const int GR_G = 4;
            float* sW = sm;
            float* sX = sm + 49152;

            int grp = bid / 14, seg = bid - grp * 14;
            int t = grp % 5;
            int isF = grp / 5;
            int b = (level - 1) * 5 + t;
            int nS = g_noff[b], cnt = g_noff[b + 1] - nS;

            const float* agg = isF ? g_aggf : g_aggs;
            float* hout = isF ? hf : hs;
            const float* wgp = (isF ? g_Gfwih_t : g_Gswih_t) + t * 49152;
            const float* bih = (isF ? Gf_bih : Gs_bih) + t * 384;
            const float* bhh = (isF ? Gf_bhh : Gs_bhh) + t * 384;

            int nw = 14 * 8;
            int wgi = seg * 8 + w;
            int ws = nS + (int)(((long long)cnt * wgi) / nw);
            int we = nS + (int)(((long long)cnt * (wgi + 1)) / nw);
            float* myX = sX + w * GR_G * 128;

            float4 xr[GR_G];
            int nr[GR_G];
            {
                int nb = we - ws;
#pragma unroll
                for (int g = 0; g < GR_G; g++) {
                    xr[g] = make_float4(0.f, 0.f, 0.f, 0.f);
                    nr[g] = 0;
                    if (g < nb) {
                        nr[g] = g_nodes[ws + g];
                        xr[g] = ((const float4*)(agg + nr[g] * 128))[lane];
                    }
                }
            }
            stage_w_vec(sW, wgp, 3, 32, tid, 256);
            float4 bRi = ((const float4*)bih)[lane];
            float4 bRh = ((const float4*)bhh)[lane];
            float4 bZi = ((const float4*)(bih + 128))[lane];
            float4 bZh = ((const float4*)(bhh + 128))[lane];
            float4 bNi = ((const float4*)(bih + 256))[lane];
            float4 bNh = ((const float4*)(bhh + 256))[lane];
            float bR[4] = {bRi.x + bRh.x, bRi.y + bRh.y, bRi.z + bRh.z, bRi.w + bRh.w};
            float bZ[4] = {bZi.x + bZh.x, bZi.y + bZh.y, bZi.z + bZh.z, bZi.w + bZh.w};
            float bNiA[4] = {bNi.x, bNi.y, bNi.z, bNi.w};
            float bNhA[4] = {bNh.x, bNh.y, bNh.z, bNh.w};
            __syncthreads();

            for (int base = ws; base < we; base += GR_G) {
                int nn = min(GR_G, we - base);
                int nc[GR_G];
#pragma unroll
                for (int g = 0; g < GR_G; g++) {
                    ((float4*)(myX + g * 128))[lane] = xr[g];
                    nc[g] = nr[g];
                }
                __syncwarp();
                if (base + GR_G < we) {
                    int nb = we - (base + GR_G);
#pragma unroll
                    for (int g = 0; g < GR_G; g++) {
                        xr[g] = make_float4(0.f, 0.f, 0.f, 0.f);
                        nr[g] = 0;
                        if (g < nb) {
                            nr[g] = g_nodes[base + GR_G + g];
                            xr[g] = ((const float4*)(agg + nr[g] * 128))[lane];
                        }
                    }
                }
                unsigned long long acc[GR_G][12];
                gemm_g<GR_G, 12>(sW, myX, lane, acc);
#pragma unroll
                for (int g = 0; g < GR_G; g++) {
                    if (g < nn) {
                        float o[4];
#pragma unroll
                        for (int oi = 0; oi < 4; oi++) {
                            float r = sigmoidf_(unpack_sum(acc[g][oi]) + bR[oi]);
                            float z = sigmoidf_(unpack_sum(acc[g][oi + 4]) + bZ[oi]);
                            float n = tanhf(unpack_sum(acc[g][oi + 8]) + bNiA[oi] + r * bNhA[oi]);
                            o[oi] = (1.f - z) * n;
                        }
                        ((float4*)(hout + nc[g] * 128))[lane] =
                            make_float4(o[0], o[1], o[2], o[3]);
                    }
                }
                __syncwarp();
            }
        }
        gbar(++tgt);
    }
}

// ---------------- host launch ----------------
extern "C" void kernel_launch(void* const* d_in, const int* in_sizes, int n_in,
                              void* d_out, int out_size) {
    const float* hs_init = (const float*)d_in[0];
    const float* Ws1 = (const float*)d_in[1];
    const float* bs1 = (const float*)d_in[2];
    const float* Ws2 = (const float*)d_in[3];
    const float* bs2 = (const float*)d_in[4];
    const float* Wf1 = (const float*)d_in[5];
    const float* bf1 = (const float*)d_in[6];
    const float* Wf2 = (const float*)d_in[7];
    const float* bf2 = (const float*)d_in[8];
    const float* Wnf1 = (const float*)d_in[9];
    const float* bnf1 = (const float*)d_in[10];
    const float* Wnf2 = (const float*)d_in[11];
    const float* bnf2 = (const float*)d_in[12];
    const float* Gs_wih = (const float*)d_in[13];
    const float* Gs_bih = (const float*)d_in[15];
    const float* Gs_bhh = (const float*)d_in[16];
    const float* Gf_wih = (const float*)d_in[17];
    const float* Gf_bih = (const float*)d_in[19];
    const float* Gf_bhh = (const float*)d_in[20];
    const int* edge_index = (const int*)d_in[21];
    const int* gate = (const int*)d_in[22];
    const int* flev = (const int*)d_in[23];

    float* hs = (float*)d_out;
    float* hf = hs + NN * DD;

    cudaFuncSetAttribute(k_all, cudaFuncAttributeMaxDynamicSharedMemorySize, 229376);

    k_all<<<NBLK, NTHR, 229376>>>(hs_init, gate, Ws1, bs1, Ws2, bs2, Wf1, bf1, Wf2, bf2,
                                  Wnf1, bnf1, Wnf2, bnf2, Gs_wih, Gs_bih, Gs_bhh,
                                  Gf_wih, Gf_bih, Gf_bhh, edge_index, flev, hs, hf);
}

// round 13
// speedup vs baseline: 1.0417x; 1.0417x over previous
#include <cuda_runtime.h>
#include <cuda_bf16.h>
#include <math.h>
#include <stdint.h>

#define NN   20000
#define DD   128
#define EE   60000
#define PERL 4000
#define NB   20

// ---------------- device scratch ----------------
__device__ float g_aggs[NN * DD];
__device__ float g_aggf[NN * DD];
__device__ float g_Wf1t[4 * 2 * DD * DD];
__device__ float g_Wf2t[4 * DD * DD];
__device__ float g_Wnf1t[DD * DD];
__device__ float g_Wnf2t[DD * DD];
__device__ float g_Gswih_t[5 * 3 * DD * DD];
__device__ float g_Gfwih_t[5 * 3 * DD * DD];
// bf16 hi/lo struct weights, K-major [t][k][n] (dense pitch 128)
__device__ unsigned short g_B1h[5 * 16384];
__device__ unsigned short g_B1l[5 * 16384];
__device__ unsigned short g_B2h[5 * 16384];
__device__ unsigned short g_B2l[5 * 16384];
__device__ int g_esrc[EE];
__device__ int g_edst[EE];
__device__ int g_ecnt[NB];
__device__ int g_eoff[NB + 1];
__device__ int g_ecur[NB];
__device__ int g_nodes[NN];
__device__ int g_ncnt[NB];
__device__ int g_noff[NB + 1];
__device__ int g_ncur[NB];

__device__ __forceinline__ int code2t(int c) {
    switch (c) {
        case 1: return 3;
        case 2: return 1;
        case 3: return 0;
        case 4: return 4;
        default: return 2;
    }
}
__device__ __forceinline__ float sigmoidf_(float x) { return 1.f / (1.f + expf(-x)); }
__device__ __forceinline__ void fma2(unsigned long long& d, unsigned long long a,
                                     unsigned long long b) {
    asm("fma.rn.f32x2 %0, %1, %2, %0;" : "+l"(d) : "l"(a), "l"(b));
}
__device__ __forceinline__ float unpack_sum(unsigned long long a) {
    float lo, hi;
    asm("mov.b64 {%0, %1}, %2;" : "=f"(lo), "=f"(hi) : "l"(a));
    return lo + hi;
}
__device__ __forceinline__ uint32_t smem_u32(const void* p) {
    uint32_t a;
    asm("{ .reg .u64 t; cvta.to.shared.u64 t, %1; cvt.u32.u64 %0, t; }" : "=r"(a) : "l"(p));
    return a;
}
__device__ __forceinline__ unsigned pack_hi(float a, float b, float& ra, float& rb) {
    __nv_bfloat162 h;
    h.x = __float2bfloat16(a); h.y = __float2bfloat16(b);
    ra = a - __bfloat162float(h.x); rb = b - __bfloat162float(h.y);
    return *reinterpret_cast<unsigned*>(&h);
}
__device__ __forceinline__ unsigned pack_bf2(float a, float b) {
    __nv_bfloat162 h;
    h.x = __float2bfloat16(a); h.y = __float2bfloat16(b);
    return *reinterpret_cast<unsigned*>(&h);
}

// ---------------- mma.sync / ldmatrix (base PTX, sm_80+) ----------------
__device__ __forceinline__ void ldsm4(unsigned* r, unsigned a) {
    asm volatile("ldmatrix.sync.aligned.m8n8.x4.shared.b16 {%0,%1,%2,%3}, [%4];"
                 : "=r"(r[0]), "=r"(r[1]), "=r"(r[2]), "=r"(r[3]) : "r"(a));
}
__device__ __forceinline__ void ldsm4t(unsigned* r, unsigned a) {
    asm volatile("ldmatrix.sync.aligned.m8n8.x4.trans.shared.b16 {%0,%1,%2,%3}, [%4];"
                 : "=r"(r[0]), "=r"(r[1]), "=r"(r[2]), "=r"(r[3]) : "r"(a));
}
__device__ __forceinline__ void mma16816(float* d, const unsigned* a, unsigned b0,
                                         unsigned b1) {
    asm volatile("mma.sync.aligned.m16n8k16.row.col.f32.bf16.bf16.f32 "
                 "{%0,%1,%2,%3},{%4,%5,%6,%7},{%8,%9},{%0,%1,%2,%3};"
                 : "+f"(d[0]), "+f"(d[1]), "+f"(d[2]), "+f"(d[3])
                 : "r"(a[0]), "r"(a[1]), "r"(a[2]), "r"(a[3]), "r"(b0), "r"(b1));
}

#define PH 136   // halves pitch for X and W smem tiles (272B rows, conflict-free ldmatrix)
// struct smem byte offsets
#define SW1H_B 0
#define SW1L_B 34816
#define SW2H_B 69632
#define SW2L_B 104448
#define SX_B   139264   // + w*8704 : Xh(4352) Xl(4352)
#define SB1_B  208896
#define SB2_B  209408

// one 16x128x128 layer: D[16 ntiles][4], 3-term bf16 hi/lo
__device__ __forceinline__ void mma_layer(unsigned xh, unsigned xl, unsigned wh,
                                          unsigned wl, int lane, float (&D)[16][4]) {
#pragma unroll
    for (int j = 0; j < 16; j++)
#pragma unroll
        for (int q = 0; q < 4; q++) D[j][q] = 0.f;
    unsigned arow = (lane & 7) + ((lane >> 3) & 1) * 8;
    unsigned aoff = (arow * PH + ((lane >> 4) << 3)) * 2;
    unsigned brow0 = (lane & 7) + ((lane >> 3) & 1) * 8;
    unsigned bc = ((lane >> 4) << 3);
#pragma unroll
    for (int k = 0; k < 8; k++) {
        unsigned Ah[4], Al[4];
        ldsm4(Ah, xh + aoff + k * 32);
        ldsm4(Al, xl + aoff + k * 32);
#pragma unroll
        for (int j2 = 0; j2 < 8; j2++) {
            unsigned bb = (((unsigned)(k * 16) + brow0) * PH + (unsigned)(j2 * 16) + bc) * 2;
            unsigned Bh[4], Bl[4];
            ldsm4t(Bh, wh + bb);
            ldsm4t(Bl, wl + bb);
            mma16816(D[2 * j2], Ah, Bh[0], Bh[1]);
            mma16816(D[2 * j2], Al, Bh[0], Bh[1]);
            mma16816(D[2 * j2], Ah, Bl[0], Bl[1]);
            mma16816(D[2 * j2 + 1], Ah, Bh[2], Bh[3]);
            mma16816(D[2 * j2 + 1], Al, Bh[2], Bh[3]);
            mma16816(D[2 * j2 + 1], Ah, Bl[2], Bl[3]);
        }
    }
}

// ---------------- prep ----------------
__device__ __forceinline__ void tr1(const float* __restrict__ src, float* __restrict__ dst,
                                    int idx, int K, int J) {
    int m = idx / (K * J);
    int r = idx - m * (K * J);
    int k = r / J;
    int j = r - k * J;
    dst[m * K * J + j * K + k] = src[idx];
}

#define INIT_TOTAL (NN * DD)
#define PREP_TOTAL 720896
__global__ void k_init(const float* __restrict__ hs_init, const int* __restrict__ gate,
                       float* __restrict__ hs, float* __restrict__ hf,
                       const float* __restrict__ Ws1, const float* __restrict__ Ws2,
                       const float* __restrict__ Wf1, const float* __restrict__ Wf2,
                       const float* __restrict__ Wnf1, const float* __restrict__ Wnf2,
                       const float* __restrict__ Gs, const float* __restrict__ Gf,
                       const int* __restrict__ ei, const int* __restrict__ flev) {
    int stride = gridDim.x * blockDim.x;
    int tid0 = blockIdx.x * blockDim.x + threadIdx.x;
    {
        int i = tid0;
        if (i < EE) {
            int dst = ei[EE + i];
            atomicAdd(&g_ecnt[(flev[dst] - 1) * 5 + code2t(gate[dst])], 1);
        }
        int v = i + PERL;
        if (i < NN - PERL) {
            atomicAdd(&g_ncnt[(flev[v] - 1) * 5 + code2t(gate[v])], 1);
        }
    }
    for (int i = tid0; i < INIT_TOTAL; i += stride) {
        int v = i >> 7;
        hs[i] = (gate[v] == 0) ? hs_init[i] : 0.f;
        hf[i] = 0.f;
        g_aggs[i] = 0.f;
        g_aggf[i] = 0.f;
    }
    for (int i = tid0; i < PREP_TOTAL; i += stride) {
        int idx = i;
        if (idx < 131072) { tr1(Wf1, g_Wf1t, idx, 256, 128); continue; }
        idx -= 131072;
        if (idx < 65536) { tr1(Wf2, g_Wf2t, idx, 128, 128); continue; }
        idx -= 65536;
        if (idx < 16384) { tr1(Wnf1, g_Wnf1t, idx, 128, 128); continue; }
        idx -= 16384;
        if (idx < 16384) { tr1(Wnf2, g_Wnf2t, idx, 128, 128); continue; }
        idx -= 16384;
        if (idx < 245760) { tr1(Gs, g_Gswih_t, idx, 128, 384); continue; }
        idx -= 245760;
        tr1(Gf, g_Gfwih_t, idx, 128, 384);
    }
    // bf16 hi/lo struct weights, K-major direct copy
    for (int i = tid0; i < 5 * 16384; i += stride) {
        float v1 = Ws1[i];
        __nv_bfloat16 h1 = __float2bfloat16(v1);
        __nv_bfloat16 l1 = __float2bfloat16(v1 - __bfloat162float(h1));
        g_B1h[i] = *reinterpret_cast<unsigned short*>(&h1);
        g_B1l[i] = *reinterpret_cast<unsigned short*>(&l1);
        float v2 = Ws2[i];
        __nv_bfloat16 h2 = __float2bfloat16(v2);
        __nv_bfloat16 l2 = __float2bfloat16(v2 - __bfloat162float(h2));
        g_B2h[i] = *reinterpret_cast<unsigned short*>(&h2);
        g_B2l[i] = *reinterpret_cast<unsigned short*>(&l2);
    }
}

__global__ void k_scan() {
    if (threadIdx.x == 0 && blockIdx.x == 0) {
        int s = 0, t = 0;
        for (int b = 0; b < NB; b++) {
            g_eoff[b] = s; g_ecur[b] = s; s += g_ecnt[b];
            g_noff[b] = t; g_ncur[b] = t; t += g_ncnt[b];
            g_ecnt[b] = 0;
            g_ncnt[b] = 0;
        }
        g_eoff[NB] = s;
        g_noff[NB] = t;
    }
}

__global__ void k_scatter(const int* __restrict__ ei, const int* __restrict__ gate,
                          const int* __restrict__ flev) {
    __shared__ int se_cnt[NB], se_base[NB], se_cur[NB];
    __shared__ int sn_cnt[NB], sn_base[NB], sn_cur[NB];
    int tid = threadIdx.x;
    if (tid < NB) {
        se_cnt[tid] = 0; sn_cnt[tid] = 0;
        se_cur[tid] = 0; sn_cur[tid] = 0;
    }
    __syncthreads();
    int i = blockIdx.x * blockDim.x + tid;
    int eb = -1, esrc = 0, edst = 0;
    if (i < EE) {
        esrc = ei[i]; edst = ei[EE + i];
        eb = (flev[edst] - 1) * 5 + code2t(gate[edst]);
        atomicAdd(&se_cnt[eb], 1);
    }
    int nb = -1, v = i + PERL;
    if (i < NN - PERL) {
        nb = (flev[v] - 1) * 5 + code2t(gate[v]);
        atomicAdd(&sn_cnt[nb], 1);
    }
    __syncthreads();
    if (tid < NB) {
        if (se_cnt[tid] > 0) se_base[tid] = atomicAdd(&g_ecur[tid], se_cnt[tid]);
        if (sn_cnt[tid] > 0) sn_base[tid] = atomicAdd(&g_ncur[tid], sn_cnt[tid]);
    }
    __syncthreads();
    if (eb >= 0) {
        int p = se_base[eb] + atomicAdd(&se_cur[eb], 1);
        g_esrc[p] = esrc;
        g_edst[p] = edst;
    }
    if (nb >= 0) {
        int p = sn_base[nb] + atomicAdd(&sn_cur[nb], 1);
        g_nodes[p] = v;
    }
}

// ---------------- fp32 staging + warp GEMM (func/GRU) ----------------
__device__ __forceinline__ void stage_w_vec(float* __restrict__ dst,
                                            const float* __restrict__ src,
                                            int nblk, int k4n, int tid, int nthr) {
    float4* d = (float4*)dst;
    const float4* sp = (const float4*)src;
    int tot = nblk * 128 * k4n;
    for (int i = tid; i < tot; i += nthr) {
        int r = i / k4n;
        int c = i - r * k4n;
        int gb = r >> 7, rr = r & 127;
        int lane = rr & 31, oi = rr >> 5;
        int srow = (gb << 7) + lane * 4 + oi;
        d[r * k4n + (c ^ (r & 7))] = sp[srow * k4n + c];
    }
}
__device__ __forceinline__ void stage_w_f1(float* __restrict__ dst,
                                           const float* __restrict__ src,
                                           int tid, int nthr) {
    float4* d = (float4*)dst;
    const float4* sp = (const float4*)src;
    for (int i = tid; i < 8192; i += nthr) {
        int h = i >> 12;
        int r = (i >> 5) & 127;
        int c = i & 31;
        int lane = r & 31, oi = r >> 5;
        int srow = lane * 4 + oi;
        d[h * 4096 + r * 32 + (c ^ (r & 7))] = sp[srow * 64 + h * 32 + c];
    }
}
template <int G, int NOUT, int K4N, int XS4, bool ZERO>
__device__ __forceinline__ void gemm_p(const float* __restrict__ sW,
                                       const float* __restrict__ sX, int lane,
                                       unsigned long long (&acc)[G][NOUT]) {
    const ulonglong2* wU = (const ulonglong2*)sW;
    const ulonglong2* xU = (const ulonglong2*)sX;
    int s = lane & 7;
    if (ZERO) {
#pragma unroll
        for (int g = 0; g < G; g++)
#pragma unroll
            for (int oi = 0; oi < NOUT; oi++) acc[g][oi] = 0ull;
    }
#pragma unroll 8
    for (int k4 = 0; k4 < K4N; k4++) {
        int kk = k4 ^ s;
        ulonglong2 xv[G];
#pragma unroll
        for (int g = 0; g < G; g++) xv[g] = xU[g * XS4 + k4];
#pragma unroll
        for (int oi = 0; oi < NOUT; oi++) {
            ulonglong2 wv = wU[(oi * 32 + lane) * K4N + kk];
#pragma unroll
            for (int g = 0; g < G; g++) {
                fma2(acc[g][oi], xv[g].x, wv.x);
                fma2(acc[g][oi], xv[g].y, wv.y);
            }
        }
    }
}

// ---------------- fused edge kernel ----------------
// blocks 0..29: mma struct (6 per gate type); 30..143: fp32 func (25/14/25/25/25)
#define E_GRID 144
#define E_SMEM 229376
__global__ void __launch_bounds__(256, 1)
k_edges(const float* __restrict__ hs, const float* __restrict__ hf,
        const float* __restrict__ bs1, const float* __restrict__ bs2,
        const float* __restrict__ bf1, const float* __restrict__ bf2,
        const float* __restrict__ bnf1, const float* __restrict__ bnf2, int level) {
    extern __shared__ float sm[];
    int bid = blockIdx.x;
    int tid = threadIdx.x, w = tid >> 5, lane = tid & 31;

    if (bid < 30) {
        // ============== struct via mma.sync bf16 3-term ==============
        char* smc = (char*)sm;
        uint32_t sb = smem_u32(smc);
        int t = bid / 6, seg = bid % 6;
        int b = (level - 1) * 5 + t;
        int eS = g_eoff[b], cnt = g_eoff[b + 1] - eS;
        int ws = eS + (int)(((long long)cnt * seg) / 6);
        int we = eS + (int)(((long long)cnt * (seg + 1)) / 6);

        // stage bf16 weights (dense pitch 64 u32 -> smem pitch 68 u32)
        for (int i = tid; i < 4 * 8192; i += 256) {
            int a = i >> 13, r = (i >> 6) & 127, c = i & 63;
            const unsigned* srcp;
            unsigned off;
            switch (a) {
                case 0: srcp = (const unsigned*)(g_B1h + (t << 14)); off = SW1H_B; break;
                case 1: srcp = (const unsigned*)(g_B1l + (t << 14)); off = SW1L_B; break;
                case 2: srcp = (const unsigned*)(g_B2h + (t << 14)); off = SW2H_B; break;
                default: srcp = (const unsigned*)(g_B2l + (t << 14)); off = SW2L_B; break;
            }
            ((unsigned*)(smc + off))[r * 68 + c] = srcp[r * 64 + c];
        }
        if (tid < 128) {
            ((float*)(smc + SB1_B))[tid] = bs1[t * 128 + tid];
            ((float*)(smc + SB2_B))[tid] = bs2[t * 128 + tid];
        }
        __syncthreads();

        const float* sB1 = (const float*)(smc + SB1_B);
        const float* sB2 = (const float*)(smc + SB2_B);
        unsigned xh = sb + SX_B + w * 8704;
        unsigned xl = xh + 4352;
        char* xhc = smc + SX_B + w * 8704;
        float* Dt = (float*)xhc;  // fp32 scratch (pitch 132), reused after layer 2
        int cj = (lane & 3) * 2;
        int ra = lane >> 2;

        for (int tile = ws + w * 16; tile < we; tile += 128) {
            int ne = min(16, we - tile);
            int srcr = 0, dstr = 0;
            if (lane < ne) {
                srcr = g_esrc[tile + lane];
                dstr = g_edst[tile + lane];
            }
            // gather + hi/lo split into X tiles
            for (int r = 0; r < ne; r++) {
                int sv = __shfl_sync(0xffffffffu, srcr, r);
                float4 v = ((const float4*)(hs + sv * 128))[lane];
                float l0, l1, l2, l3;
                unsigned h01 = pack_hi(v.x, v.y, l0, l1);
                unsigned h23 = pack_hi(v.z, v.w, l2, l3);
                unsigned* xp = (unsigned*)(xhc + (r * PH + lane * 4) * 2);
                xp[0] = h01; xp[1] = h23;
                unsigned* lp = (unsigned*)(xhc + 4352 + (r * PH + lane * 4) * 2);
                lp[0] = pack_bf2(l0, l1);
                lp[1] = pack_bf2(l2, l3);
            }
            __syncwarp();
            float D[16][4];
            mma_layer(xh, xl, sb + SW1H_B, sb + SW1L_B, lane, D);
            __syncwarp();
            // relu + bias -> X hi/lo
#pragma unroll
            for (int j = 0; j < 16; j++) {
                int c = j * 8 + cj;
                float y0 = fmaxf(D[j][0] + sB1[c], 0.f);
                float y1 = fmaxf(D[j][1] + sB1[c + 1], 0.f);
                float y2 = fmaxf(D[j][2] + sB1[c], 0.f);
                float y3 = fmaxf(D[j][3] + sB1[c + 1], 0.f);
                float l0, l1;
                unsigned hp = pack_hi(y0, y1, l0, l1);
                *(unsigned*)(xhc + (ra * PH + c) * 2) = hp;
                *(unsigned*)(xhc + 4352 + (ra * PH + c) * 2) = pack_bf2(l0, l1);
                unsigned hp2 = pack_hi(y2, y3, l0, l1);
                *(unsigned*)(xhc + ((ra + 8) * PH + c) * 2) = hp2;
                *(unsigned*)(xhc + 4352 + ((ra + 8) * PH + c) * 2) = pack_bf2(l0, l1);
            }
            __syncwarp();
            mma_layer(xh, xl, sb + SW2H_B, sb + SW2L_B, lane, D);
            __syncwarp();
            // D + bias2 -> fp32 scratch
#pragma unroll
            for (int j = 0; j < 16; j++) {
                int c = j * 8 + cj;
                Dt[ra * 132 + c] = D[j][0] + sB2[c];
                Dt[ra * 132 + c + 1] = D[j][1] + sB2[c + 1];
                Dt[(ra + 8) * 132 + c] = D[j][2] + sB2[c];
                Dt[(ra + 8) * 132 + c + 1] = D[j][3] + sB2[c + 1];
            }
            __syncwarp();
            // float4 atomic scatter
            for (int r = 0; r < ne; r++) {
                int dv = __shfl_sync(0xffffffffu, dstr, r);
                float4 q = make_float4(Dt[r * 132 + lane * 4], Dt[r * 132 + lane * 4 + 1],
                                       Dt[r * 132 + lane * 4 + 2],
                                       Dt[r * 132 + lane * 4 + 3]);
                atomicAdd((float4*)&g_aggs[dv * 128 + lane * 4], q);
            }
            __syncwarp();
        }
        return;
    }

    // ============== functional path (fp32, R11-proven) ==============
    {
        int r = bid - 30;
        int t, seg, nseg;
        if (r < 25)      { t = 0; seg = r;      nseg = 25; }
        else if (r < 39) { t = 1; seg = r - 25; nseg = 14; }
        else if (r < 64) { t = 2; seg = r - 39; nseg = 25; }
        else if (r < 89) { t = 3; seg = r - 64; nseg = 25; }
        else             { t = 4; seg = r - 89; nseg = 25; }
        int b = (level - 1) * 5 + t;
        int eS = g_eoff[b], cnt = g_eoff[b + 1] - eS;
        int nw = nseg * 8;
        int wgi = seg * 8 + w;
        int ws = eS + (int)(((long long)cnt * wgi) / nw);
        int we = eS + (int)(((long long)cnt * (wgi + 1)) / nw);

        const int G = 8;
        float* sW1 = sm;
        float* sW2 = sm + 32768;
        float* myX = sm + 49152 + w * (G * 128);

        bool isnot = (t == 1);
        const float *W2g, *b1g, *b2g;
        if (isnot) {
            stage_w_vec(sW1, g_Wnf1t, 1, 32, tid, 256);
            W2g = g_Wnf2t; b1g = bnf1; b2g = bnf2;
        } else {
            int fi = (t == 0) ? 0 : (t == 2) ? 1 : (t == 3) ? 2 : 3;
            stage_w_f1(sW1, g_Wf1t + fi * 32768, tid, 256);
            W2g = g_Wf2t + fi * 16384;
            b1g = bf1 + fi * 128;
            b2g = bf2 + fi * 128;
        }
        stage_w_vec(sW2, W2g, 1, 32, tid, 256);

        float4 xa[G], xb[G];
        int dr[G];
        {
            int nb = we - ws;
#pragma unroll
            for (int g = 0; g < G; g++) {
                xa[g] = make_float4(0.f, 0.f, 0.f, 0.f);
                xb[g] = xa[g];
                dr[g] = 0;
                if (g < nb) {
                    int sn = g_esrc[ws + g];
                    dr[g] = g_edst[ws + g];
                    if (isnot) {
                        xa[g] = ((const float4*)(hf + sn * 128))[lane];
                    } else {
                        xa[g] = ((const float4*)(hs + sn * 128))[lane];
                        xb[g] = ((const float4*)(hf + sn * 128))[lane];
                    }
                }
            }
        }
        float4 b1v = ((const float4*)b1g)[lane];
        float4 b2v = ((const float4*)b2g)[lane];
        __syncthreads();

        for (int base = ws; base < we; base += G) {
            int ne = min(G, we - base);
            int dc[G];
#pragma unroll
            for (int g = 0; g < G; g++) {
                ((float4*)(myX + g * 128))[lane] = xa[g];
                dc[g] = dr[g];
            }
            __syncwarp();
            int nb2 = we - (base + G);
            if (nb2 > 0) {
#pragma unroll
                for (int g = 0; g < G; g++) {
                    xa[g] = make_float4(0.f, 0.f, 0.f, 0.f);
                    if (g < nb2) {
                        int sn = g_esrc[base + G + g];
                        xa[g] = ((const float4*)((isnot ? hf : hs) + sn * 128))[lane];
                    }
                }
            }
            unsigned long long a1[G][4];
            gemm_p<G, 4, 32, 32, true>(sW1, myX, lane, a1);
            __syncwarp();
            if (!isnot) {
#pragma unroll
                for (int g = 0; g < G; g++)
                    ((float4*)(myX + g * 128))[lane] = xb[g];
                __syncwarp();
                if (nb2 > 0) {
#pragma unroll
                    for (int g = 0; g < G; g++) {
                        xb[g] = make_float4(0.f, 0.f, 0.f, 0.f);
                        if (g < nb2) {
                            int sn = g_esrc[base + G + g];
                            xb[g] = ((const float4*)(hf + sn * 128))[lane];
                        }
                    }
                }
                gemm_p<G, 4, 32, 32, false>(sW1 + 16384, myX, lane, a1);
                __syncwarp();
            }
            if (nb2 > 0) {
#pragma unroll
                for (int g = 0; g < G; g++)
                    dr[g] = (g < nb2) ? g_edst[base + G + g] : 0;
            }
#pragma unroll
            for (int g = 0; g < G; g++) {
                float4 y = make_float4(fmaxf(unpack_sum(a1[g][0]) + b1v.x, 0.f),
                                       fmaxf(unpack_sum(a1[g][1]) + b1v.y, 0.f),
                                       fmaxf(unpack_sum(a1[g][2]) + b1v.z, 0.f),
                                       fmaxf(unpack_sum(a1[g][3]) + b1v.w, 0.f));
                ((float4*)(myX + g * 128))[lane] = y;
            }
            __syncwarp();
            unsigned long long a2[G][4];
            gemm_p<G, 4, 32, 32, true>(sW2, myX, lane, a2);
#pragma unroll
            for (int g = 0; g < G; g++) {
                if (g < ne) {
                    float4 v = make_float4(unpack_sum(a2[g][0]) + b2v.x,
                                           unpack_sum(a2[g][1]) + b2v.y,
                                           unpack_sum(a2[g][2]) + b2v.z,
                                           unpack_sum(a2[g][3]) + b2v.w);
                    atomicAdd((float4*)&g_aggf[dc[g] * 128 + lane * 4], v);
                }
            }
            __syncwarp();
        }
    }
}

// ---------------- GRU (h == 0), fused s/f ----------------
#define GR_NW 8
#define GR_G 4
__global__ void __launch_bounds__(256, 1)
k_gru(const float* __restrict__ Gs_bih, const float* __restrict__ Gs_bhh,
      const float* __restrict__ Gf_bih, const float* __restrict__ Gf_bhh,
      float* __restrict__ hs, float* __restrict__ hf, int level) {
    extern __shared__ float sm[];
    float* sW = sm;
    float* sX = sm + 49152;

    int t = blockIdx.y % 5;
    int isF = blockIdx.y / 5;
    int b = (level - 1) * 5 + t;
    int nS = g_noff[b], cnt = g_noff[b + 1] - nS;

    const float* agg = isF ? g_aggf : g_aggs;
    float* hout = isF ? hf : hs;
    const float* wgp = (isF ? g_Gfwih_t : g_Gswih_t) + t * 49152;
    const float* bih = (isF ? Gf_bih : Gs_bih) + t * 384;
    const float* bhh = (isF ? Gf_bhh : Gs_bhh) + t * 384;

    int w = threadIdx.x >> 5, lane = threadIdx.x & 31;
    int nw = gridDim.x * GR_NW;
    int wgi = blockIdx.x * GR_NW + w;
    int ws = nS + (int)(((long long)cnt * wgi) / nw);
    int we = nS + (int)(((long long)cnt * (wgi + 1)) / nw);
    float* myX = sX + w * GR_G * 128;

    float4 xr[GR_G];
    int nr[GR_G];
    {
        int nb = we - ws;
#pragma unroll
        for (int g = 0; g < GR_G; g++) {
            xr[g] = make_float4(0.f, 0.f, 0.f, 0.f);
            nr[g] = 0;
            if (g < nb) {
                nr[g] = g_nodes[ws + g];
                xr[g] = ((const float4*)(agg + nr[g] * 128))[lane];
            }
        }
    }
    stage_w_vec(sW, wgp, 3, 32, threadIdx.x, 256);
    float4 bRi = ((const float4*)bih)[lane];
    float4 bRh = ((const float4*)bhh)[lane];
    float4 bZi = ((const float4*)(bih + 128))[lane];
    float4 bZh = ((const float4*)(bhh + 128))[lane];
    float4 bNi = ((const float4*)(bih + 256))[lane];
    float4 bNh = ((const float4*)(bhh + 256))[lane];
    float bR[4] = {bRi.x + bRh.x, bRi.y + bRh.y, bRi.z + bRh.z, bRi.w + bRh.w};
    float bZ[4] = {bZi.x + bZh.x, bZi.y + bZh.y, bZi.z + bZh.z, bZi.w + bZh.w};
    float bNiA[4] = {bNi.x, bNi.y, bNi.z, bNi.w};
    float bNhA[4] = {bNh.x, bNh.y, bNh.z, bNh.w};
    __syncthreads();

    for (int base = ws; base < we; base += GR_G) {
        int nn = min(GR_G, we - base);
        int nc[GR_G];
#pragma unroll
        for (int g = 0; g < GR_G; g++) {
            ((float4*)(myX + g * 128))[lane] = xr[g];
            nc[g] = nr[g];
        }
        __syncwarp();
        if (base + GR_G < we) {
            int nb = we - (base + GR_G);
#pragma unroll
            for (int g = 0; g < GR_G; g++) {
                xr[g] = make_float4(0.f, 0.f, 0.f, 0.f);
                nr[g] = 0;
                if (g < nb) {
                    nr[g] = g_nodes[base + GR_G + g];
                    xr[g] = ((const float4*)(agg + nr[g] * 128))[lane];
                }
            }
        }
        unsigned long long acc[GR_G][12];
        gemm_p<GR_G, 12, 32, 32, true>(sW, myX, lane, acc);
#pragma unroll
        for (int g = 0; g < GR_G; g++) {
            if (g < nn) {
                float o[4];
#pragma unroll
                for (int oi = 0; oi < 4; oi++) {
                    float r = sigmoidf_(unpack_sum(acc[g][oi]) + bR[oi]);
                    float z = sigmoidf_(unpack_sum(acc[g][oi + 4]) + bZ[oi]);
                    float n = tanhf(unpack_sum(acc[g][oi + 8]) + bNiA[oi] + r * bNhA[oi]);
                    o[oi] = (1.f - z) * n;
                }
                ((float4*)(hout + nc[g] * 128))[lane] = make_float4(o[0], o[1], o[2], o[3]);
            }
        }
        __syncwarp();
    }
}

// ---------------- host launch ----------------
extern "C" void kernel_launch(void* const* d_in, const int* in_sizes, int n_in,
                              void* d_out, int out_size) {
    const float* hs_init = (const float*)d_in[0];
    const float* Ws1 = (const float*)d_in[1];
    const float* bs1 = (const float*)d_in[2];
    const float* Ws2 = (const float*)d_in[3];
    const float* bs2 = (const float*)d_in[4];
    const float* Wf1 = (const float*)d_in[5];
    const float* bf1 = (const float*)d_in[6];
    const float* Wf2 = (const float*)d_in[7];
    const float* bf2 = (const float*)d_in[8];
    const float* Wnf1 = (const float*)d_in[9];
    const float* bnf1 = (const float*)d_in[10];
    const float* Wnf2 = (const float*)d_in[11];
    const float* bnf2 = (const float*)d_in[12];
    const float* Gs_wih = (const float*)d_in[13];
    const float* Gs_bih = (const float*)d_in[15];
    const float* Gs_bhh = (const float*)d_in[16];
    const float* Gf_wih = (const float*)d_in[17];
    const float* Gf_bih = (const float*)d_in[19];
    const float* Gf_bhh = (const float*)d_in[20];
    const int* edge_index = (const int*)d_in[21];
    const int* gate = (const int*)d_in[22];
    const int* flev = (const int*)d_in[23];

    float* hs = (float*)d_out;
    float* hf = hs + NN * DD;

    cudaFuncSetAttribute(k_edges, cudaFuncAttributeMaxDynamicSharedMemorySize, E_SMEM);
    cudaFuncSetAttribute(k_gru, cudaFuncAttributeMaxDynamicSharedMemorySize, 212992);

    k_init<<<1024, 256>>>(hs_init, gate, hs, hf, Ws1, Ws2, Wf1, Wf2, Wnf1, Wnf2,
                          Gs_wih, Gf_wih, edge_index, flev);
    k_scan<<<1, 1>>>();
    k_scatter<<<(EE + 255) / 256, 256>>>(edge_index, gate, flev);

    for (int level = 1; level < 5; level++) {
        k_edges<<<E_GRID, 256, E_SMEM>>>(hs, hf, bs1, bs2, bf1, bf2, bnf1, bnf2, level);
        k_gru<<<dim3(14, 10), 256, 212992>>>(Gs_bih, Gs_bhh, Gf_bih, Gf_bhh, hs, hf, level);
    }
}

// round 14
// speedup vs baseline: 1.1257x; 1.0806x over previous
#include <cuda_runtime.h>
#include <cuda_bf16.h>
#include <math.h>
#include <stdint.h>

#define NN   20000
#define DD   128
#define EE   60000
#define PERL 4000
#define NB   20

// ---------------- device scratch ----------------
__device__ float g_aggs[NN * DD];
__device__ float g_aggf[NN * DD];
__device__ float g_Wf1t[4 * 2 * DD * DD];
__device__ float g_Wf2t[4 * DD * DD];
__device__ float g_Wnf1t[DD * DD];
__device__ float g_Wnf2t[DD * DD];
__device__ float g_Gswih_t[5 * 3 * DD * DD];
__device__ float g_Gfwih_t[5 * 3 * DD * DD];
// bf16 hi/lo struct weights, K-major [t][k][n] (dense pitch 128)
__device__ unsigned short g_B1h[5 * 16384];
__device__ unsigned short g_B1l[5 * 16384];
__device__ unsigned short g_B2h[5 * 16384];
__device__ unsigned short g_B2l[5 * 16384];
__device__ int g_esrc[EE];
__device__ int g_edst[EE];
__device__ int g_ecnt[NB];
__device__ int g_eoff[NB + 1];
__device__ int g_ecur[NB];
__device__ int g_nodes[NN];
__device__ int g_ncnt[NB];
__device__ int g_noff[NB + 1];
__device__ int g_ncur[NB];

__device__ __forceinline__ int code2t(int c) {
    switch (c) {
        case 1: return 3;
        case 2: return 1;
        case 3: return 0;
        case 4: return 4;
        default: return 2;
    }
}
__device__ __forceinline__ float sigmoidf_(float x) { return 1.f / (1.f + expf(-x)); }
__device__ __forceinline__ void fma2(unsigned long long& d, unsigned long long a,
                                     unsigned long long b) {
    asm("fma.rn.f32x2 %0, %1, %2, %0;" : "+l"(d) : "l"(a), "l"(b));
}
__device__ __forceinline__ float unpack_sum(unsigned long long a) {
    float lo, hi;
    asm("mov.b64 {%0, %1}, %2;" : "=f"(lo), "=f"(hi) : "l"(a));
    return lo + hi;
}
__device__ __forceinline__ uint32_t smem_u32(const void* p) {
    uint32_t a;
    asm("{ .reg .u64 t; cvta.to.shared.u64 t, %1; cvt.u32.u64 %0, t; }" : "=r"(a) : "l"(p));
    return a;
}
__device__ __forceinline__ unsigned pack_hi(float a, float b, float& ra, float& rb) {
    __nv_bfloat162 h;
    h.x = __float2bfloat16(a); h.y = __float2bfloat16(b);
    ra = a - __bfloat162float(h.x); rb = b - __bfloat162float(h.y);
    return *reinterpret_cast<unsigned*>(&h);
}
__device__ __forceinline__ unsigned pack_bf2(float a, float b) {
    __nv_bfloat162 h;
    h.x = __float2bfloat16(a); h.y = __float2bfloat16(b);
    return *reinterpret_cast<unsigned*>(&h);
}

// ---------------- mma.sync / ldmatrix (base PTX, sm_80+) ----------------
__device__ __forceinline__ void ldsm4(unsigned* r, unsigned a) {
    asm volatile("ldmatrix.sync.aligned.m8n8.x4.shared.b16 {%0,%1,%2,%3}, [%4];"
                 : "=r"(r[0]), "=r"(r[1]), "=r"(r[2]), "=r"(r[3]) : "r"(a));
}
__device__ __forceinline__ void ldsm4t(unsigned* r, unsigned a) {
    asm volatile("ldmatrix.sync.aligned.m8n8.x4.trans.shared.b16 {%0,%1,%2,%3}, [%4];"
                 : "=r"(r[0]), "=r"(r[1]), "=r"(r[2]), "=r"(r[3]) : "r"(a));
}
__device__ __forceinline__ void mma16816(float* d, const unsigned* a, unsigned b0,
                                         unsigned b1) {
    asm volatile("mma.sync.aligned.m16n8k16.row.col.f32.bf16.bf16.f32 "
                 "{%0,%1,%2,%3},{%4,%5,%6,%7},{%8,%9},{%0,%1,%2,%3};"
                 : "+f"(d[0]), "+f"(d[1]), "+f"(d[2]), "+f"(d[3])
                 : "r"(a[0]), "r"(a[1]), "r"(a[2]), "r"(a[3]), "r"(b0), "r"(b1));
}

#define PH 136   // halves pitch for X and W smem tiles (272B rows, conflict-free ldmatrix)
// struct smem byte offsets
#define SW1H_B 0
#define SW1L_B 34816
#define SW2H_B 69632
#define SW2L_B 104448
#define SX_B   139264   // + w*8704 : Xh(4352) Xl(4352)
#define SB1_B  208896
#define SB2_B  209408

// one 16x128x128 layer: D[16 ntiles][4], 3-term bf16 hi/lo
__device__ __forceinline__ void mma_layer(unsigned xh, unsigned xl, unsigned wh,
                                          unsigned wl, int lane, float (&D)[16][4]) {
#pragma unroll
    for (int j = 0; j < 16; j++)
#pragma unroll
        for (int q = 0; q < 4; q++) D[j][q] = 0.f;
    unsigned arow = (lane & 7) + ((lane >> 3) & 1) * 8;
    unsigned aoff = (arow * PH + ((lane >> 4) << 3)) * 2;
    unsigned brow0 = (lane & 7) + ((lane >> 3) & 1) * 8;
    unsigned bc = ((lane >> 4) << 3);
#pragma unroll
    for (int k = 0; k < 8; k++) {
        unsigned Ah[4], Al[4];
        ldsm4(Ah, xh + aoff + k * 32);
        ldsm4(Al, xl + aoff + k * 32);
#pragma unroll
        for (int j2 = 0; j2 < 8; j2++) {
            unsigned bb = (((unsigned)(k * 16) + brow0) * PH + (unsigned)(j2 * 16) + bc) * 2;
            unsigned Bh[4], Bl[4];
            ldsm4t(Bh, wh + bb);
            ldsm4t(Bl, wl + bb);
            mma16816(D[2 * j2], Ah, Bh[0], Bh[1]);
            mma16816(D[2 * j2], Al, Bh[0], Bh[1]);
            mma16816(D[2 * j2], Ah, Bl[0], Bl[1]);
            mma16816(D[2 * j2 + 1], Ah, Bh[2], Bh[3]);
            mma16816(D[2 * j2 + 1], Al, Bh[2], Bh[3]);
            mma16816(D[2 * j2 + 1], Ah, Bl[2], Bl[3]);
        }
    }
}

// ---------------- prep ----------------
__device__ __forceinline__ void tr1(const float* __restrict__ src, float* __restrict__ dst,
                                    int idx, int K, int J) {
    int m = idx / (K * J);
    int r = idx - m * (K * J);
    int k = r / J;
    int j = r - k * J;
    dst[m * K * J + j * K + k] = src[idx];
}

#define INIT_TOTAL (NN * DD)
#define PREP_TOTAL 720896
__global__ void k_init(const float* __restrict__ hs_init, const int* __restrict__ gate,
                       float* __restrict__ hs, float* __restrict__ hf,
                       const float* __restrict__ Ws1, const float* __restrict__ Ws2,
                       const float* __restrict__ Wf1, const float* __restrict__ Wf2,
                       const float* __restrict__ Wnf1, const float* __restrict__ Wnf2,
                       const float* __restrict__ Gs, const float* __restrict__ Gf,
                       const int* __restrict__ ei, const int* __restrict__ flev) {
    int stride = gridDim.x * blockDim.x;
    int tid0 = blockIdx.x * blockDim.x + threadIdx.x;
    {
        int i = tid0;
        if (i < EE) {
            int dst = ei[EE + i];
            atomicAdd(&g_ecnt[(flev[dst] - 1) * 5 + code2t(gate[dst])], 1);
        }
        int v = i + PERL;
        if (i < NN - PERL) {
            atomicAdd(&g_ncnt[(flev[v] - 1) * 5 + code2t(gate[v])], 1);
        }
    }
    for (int i = tid0; i < INIT_TOTAL; i += stride) {
        int v = i >> 7;
        hs[i] = (gate[v] == 0) ? hs_init[i] : 0.f;
        hf[i] = 0.f;
        g_aggs[i] = 0.f;
        g_aggf[i] = 0.f;
    }
    for (int i = tid0; i < PREP_TOTAL; i += stride) {
        int idx = i;
        if (idx < 131072) { tr1(Wf1, g_Wf1t, idx, 256, 128); continue; }
        idx -= 131072;
        if (idx < 65536) { tr1(Wf2, g_Wf2t, idx, 128, 128); continue; }
        idx -= 65536;
        if (idx < 16384) { tr1(Wnf1, g_Wnf1t, idx, 128, 128); continue; }
        idx -= 16384;
        if (idx < 16384) { tr1(Wnf2, g_Wnf2t, idx, 128, 128); continue; }
        idx -= 16384;
        if (idx < 245760) { tr1(Gs, g_Gswih_t, idx, 128, 384); continue; }
        idx -= 245760;
        tr1(Gf, g_Gfwih_t, idx, 128, 384);
    }
    // bf16 hi/lo struct weights, K-major direct copy
    for (int i = tid0; i < 5 * 16384; i += stride) {
        float v1 = Ws1[i];
        __nv_bfloat16 h1 = __float2bfloat16(v1);
        __nv_bfloat16 l1 = __float2bfloat16(v1 - __bfloat162float(h1));
        g_B1h[i] = *reinterpret_cast<unsigned short*>(&h1);
        g_B1l[i] = *reinterpret_cast<unsigned short*>(&l1);
        float v2 = Ws2[i];
        __nv_bfloat16 h2 = __float2bfloat16(v2);
        __nv_bfloat16 l2 = __float2bfloat16(v2 - __bfloat162float(h2));
        g_B2h[i] = *reinterpret_cast<unsigned short*>(&h2);
        g_B2l[i] = *reinterpret_cast<unsigned short*>(&l2);
    }
}

__global__ void k_scan() {
    if (threadIdx.x == 0 && blockIdx.x == 0) {
        int s = 0, t = 0;
        for (int b = 0; b < NB; b++) {
            g_eoff[b] = s; g_ecur[b] = s; s += g_ecnt[b];
            g_noff[b] = t; g_ncur[b] = t; t += g_ncnt[b];
            g_ecnt[b] = 0;
            g_ncnt[b] = 0;
        }
        g_eoff[NB] = s;
        g_noff[NB] = t;
    }
}

__global__ void k_scatter(const int* __restrict__ ei, const int* __restrict__ gate,
                          const int* __restrict__ flev) {
    __shared__ int se_cnt[NB], se_base[NB], se_cur[NB];
    __shared__ int sn_cnt[NB], sn_base[NB], sn_cur[NB];
    int tid = threadIdx.x;
    if (tid < NB) {
        se_cnt[tid] = 0; sn_cnt[tid] = 0;
        se_cur[tid] = 0; sn_cur[tid] = 0;
    }
    __syncthreads();
    int i = blockIdx.x * blockDim.x + tid;
    int eb = -1, esrc = 0, edst = 0;
    if (i < EE) {
        esrc = ei[i]; edst = ei[EE + i];
        eb = (flev[edst] - 1) * 5 + code2t(gate[edst]);
        atomicAdd(&se_cnt[eb], 1);
    }
    int nb = -1, v = i + PERL;
    if (i < NN - PERL) {
        nb = (flev[v] - 1) * 5 + code2t(gate[v]);
        atomicAdd(&sn_cnt[nb], 1);
    }
    __syncthreads();
    if (tid < NB) {
        if (se_cnt[tid] > 0) se_base[tid] = atomicAdd(&g_ecur[tid], se_cnt[tid]);
        if (sn_cnt[tid] > 0) sn_base[tid] = atomicAdd(&g_ncur[tid], sn_cnt[tid]);
    }
    __syncthreads();
    if (eb >= 0) {
        int p = se_base[eb] + atomicAdd(&se_cur[eb], 1);
        g_esrc[p] = esrc;
        g_edst[p] = edst;
    }
    if (nb >= 0) {
        int p = sn_base[nb] + atomicAdd(&sn_cur[nb], 1);
        g_nodes[p] = v;
    }
}

// ---------------- fp32 staging + warp GEMM (func/GRU) ----------------
__device__ __forceinline__ void stage_w_vec(float* __restrict__ dst,
                                            const float* __restrict__ src,
                                            int nblk, int k4n, int tid, int nthr) {
    float4* d = (float4*)dst;
    const float4* sp = (const float4*)src;
    int tot = nblk * 128 * k4n;
    for (int i = tid; i < tot; i += nthr) {
        int r = i / k4n;
        int c = i - r * k4n;
        int gb = r >> 7, rr = r & 127;
        int lane = rr & 31, oi = rr >> 5;
        int srow = (gb << 7) + lane * 4 + oi;
        d[r * k4n + (c ^ (r & 7))] = sp[srow * k4n + c];
    }
}
__device__ __forceinline__ void stage_w_f1(float* __restrict__ dst,
                                           const float* __restrict__ src,
                                           int tid, int nthr) {
    float4* d = (float4*)dst;
    const float4* sp = (const float4*)src;
    for (int i = tid; i < 8192; i += nthr) {
        int h = i >> 12;
        int r = (i >> 5) & 127;
        int c = i & 31;
        int lane = r & 31, oi = r >> 5;
        int srow = lane * 4 + oi;
        d[h * 4096 + r * 32 + (c ^ (r & 7))] = sp[srow * 64 + h * 32 + c];
    }
}
template <int G, int NOUT, int K4N, int XS4, bool ZERO>
__device__ __forceinline__ void gemm_p(const float* __restrict__ sW,
                                       const float* __restrict__ sX, int lane,
                                       unsigned long long (&acc)[G][NOUT]) {
    const ulonglong2* wU = (const ulonglong2*)sW;
    const ulonglong2* xU = (const ulonglong2*)sX;
    int s = lane & 7;
    if (ZERO) {
#pragma unroll
        for (int g = 0; g < G; g++)
#pragma unroll
            for (int oi = 0; oi < NOUT; oi++) acc[g][oi] = 0ull;
    }
#pragma unroll 8
    for (int k4 = 0; k4 < K4N; k4++) {
        int kk = k4 ^ s;
        ulonglong2 xv[G];
#pragma unroll
        for (int g = 0; g < G; g++) xv[g] = xU[g * XS4 + k4];
#pragma unroll
        for (int oi = 0; oi < NOUT; oi++) {
            ulonglong2 wv = wU[(oi * 32 + lane) * K4N + kk];
#pragma unroll
            for (int g = 0; g < G; g++) {
                fma2(acc[g][oi], xv[g].x, wv.x);
                fma2(acc[g][oi], xv[g].y, wv.y);
            }
        }
    }
}

// ---------------- fused edge kernel ----------------
// blocks 0..44: mma struct (9 per gate type); 45..143: fp32 func (22/11/22/22/22)
#define E_GRID 144
#define E_SMEM 229376
__global__ void __launch_bounds__(256, 1)
k_edges(const float* __restrict__ hs, const float* __restrict__ hf,
        const float* __restrict__ bs1, const float* __restrict__ bs2,
        const float* __restrict__ bf1, const float* __restrict__ bf2,
        const float* __restrict__ bnf1, const float* __restrict__ bnf2, int level) {
    extern __shared__ float sm[];
    int bid = blockIdx.x;
    int tid = threadIdx.x, w = tid >> 5, lane = tid & 31;

    if (bid < 45) {
        // ============== struct via mma.sync bf16 3-term ==============
        char* smc = (char*)sm;
        uint32_t sb = smem_u32(smc);
        int t = bid / 9, seg = bid % 9;
        int b = (level - 1) * 5 + t;
        int eS = g_eoff[b], cnt = g_eoff[b + 1] - eS;
        int ws = eS + (int)(((long long)cnt * seg) / 9);
        int we = eS + (int)(((long long)cnt * (seg + 1)) / 9);

        // stage bf16 weights (dense pitch 64 u32 -> smem pitch 68 u32)
        for (int i = tid; i < 4 * 8192; i += 256) {
            int a = i >> 13, r = (i >> 6) & 127, c = i & 63;
            const unsigned* srcp;
            unsigned off;
            switch (a) {
                case 0: srcp = (const unsigned*)(g_B1h + (t << 14)); off = SW1H_B; break;
                case 1: srcp = (const unsigned*)(g_B1l + (t << 14)); off = SW1L_B; break;
                case 2: srcp = (const unsigned*)(g_B2h + (t << 14)); off = SW2H_B; break;
                default: srcp = (const unsigned*)(g_B2l + (t << 14)); off = SW2L_B; break;
            }
            ((unsigned*)(smc + off))[r * 68 + c] = srcp[r * 64 + c];
        }
        if (tid < 128) {
            ((float*)(smc + SB1_B))[tid] = bs1[t * 128 + tid];
            ((float*)(smc + SB2_B))[tid] = bs2[t * 128 + tid];
        }
        __syncthreads();

        const float* sB1 = (const float*)(smc + SB1_B);
        const float* sB2 = (const float*)(smc + SB2_B);
        unsigned xh = sb + SX_B + w * 8704;
        unsigned xl = xh + 4352;
        char* xhc = smc + SX_B + w * 8704;
        float* Dt = (float*)xhc;  // fp32 scratch (pitch 132), reused after layer 2
        int cj = (lane & 3) * 2;
        int ra = lane >> 2;

        for (int tile = ws + w * 16; tile < we; tile += 128) {
            int ne = min(16, we - tile);
            int srcr = 0, dstr = 0;
            if (lane < ne) {
                srcr = g_esrc[tile + lane];
                dstr = g_edst[tile + lane];
            }
            // gather + hi/lo split into X tiles
            for (int r = 0; r < ne; r++) {
                int sv = __shfl_sync(0xffffffffu, srcr, r);
                float4 v = ((const float4*)(hs + sv * 128))[lane];
                float l0, l1, l2, l3;
                unsigned h01 = pack_hi(v.x, v.y, l0, l1);
                unsigned h23 = pack_hi(v.z, v.w, l2, l3);
                unsigned* xp = (unsigned*)(xhc + (r * PH + lane * 4) * 2);
                xp[0] = h01; xp[1] = h23;
                unsigned* lp = (unsigned*)(xhc + 4352 + (r * PH + lane * 4) * 2);
                lp[0] = pack_bf2(l0, l1);
                lp[1] = pack_bf2(l2, l3);
            }
            __syncwarp();
            float D[16][4];
            mma_layer(xh, xl, sb + SW1H_B, sb + SW1L_B, lane, D);
            __syncwarp();
            // relu + bias -> X hi/lo
#pragma unroll
            for (int j = 0; j < 16; j++) {
                int c = j * 8 + cj;
                float y0 = fmaxf(D[j][0] + sB1[c], 0.f);
                float y1 = fmaxf(D[j][1] + sB1[c + 1], 0.f);
                float y2 = fmaxf(D[j][2] + sB1[c], 0.f);
                float y3 = fmaxf(D[j][3] + sB1[c + 1], 0.f);
                float l0, l1;
                unsigned hp = pack_hi(y0, y1, l0, l1);
                *(unsigned*)(xhc + (ra * PH + c) * 2) = hp;
                *(unsigned*)(xhc + 4352 + (ra * PH + c) * 2) = pack_bf2(l0, l1);
                unsigned hp2 = pack_hi(y2, y3, l0, l1);
                *(unsigned*)(xhc + ((ra + 8) * PH + c) * 2) = hp2;
                *(unsigned*)(xhc + 4352 + ((ra + 8) * PH + c) * 2) = pack_bf2(l0, l1);
            }
            __syncwarp();
            mma_layer(xh, xl, sb + SW2H_B, sb + SW2L_B, lane, D);
            __syncwarp();
            // D + bias2 -> fp32 scratch
#pragma unroll
            for (int j = 0; j < 16; j++) {
                int c = j * 8 + cj;
                Dt[ra * 132 + c] = D[j][0] + sB2[c];
                Dt[ra * 132 + c + 1] = D[j][1] + sB2[c + 1];
                Dt[(ra + 8) * 132 + c] = D[j][2] + sB2[c];
                Dt[(ra + 8) * 132 + c + 1] = D[j][3] + sB2[c + 1];
            }
            __syncwarp();
            // float4 atomic scatter
            for (int r = 0; r < ne; r++) {
                int dv = __shfl_sync(0xffffffffu, dstr, r);
                float4 q = make_float4(Dt[r * 132 + lane * 4], Dt[r * 132 + lane * 4 + 1],
                                       Dt[r * 132 + lane * 4 + 2],
                                       Dt[r * 132 + lane * 4 + 3]);
                atomicAdd((float4*)&g_aggs[dv * 128 + lane * 4], q);
            }
            __syncwarp();
        }
        return;
    }

    // ============== functional path (fp32, R11-proven) ==============
    {
        int r = bid - 45;
        int t, seg, nseg;
        if (r < 22)      { t = 0; seg = r;      nseg = 22; }
        else if (r < 33) { t = 1; seg = r - 22; nseg = 11; }
        else if (r < 55) { t = 2; seg = r - 33; nseg = 22; }
        else if (r < 77) { t = 3; seg = r - 55; nseg = 22; }
        else             { t = 4; seg = r - 77; nseg = 22; }
        int b = (level - 1) * 5 + t;
        int eS = g_eoff[b], cnt = g_eoff[b + 1] - eS;
        int nw = nseg * 8;
        int wgi = seg * 8 + w;
        int ws = eS + (int)(((long long)cnt * wgi) / nw);
        int we = eS + (int)(((long long)cnt * (wgi + 1)) / nw);

        const int G = 8;
        float* sW1 = sm;
        float* sW2 = sm + 32768;
        float* myX = sm + 49152 + w * (G * 128);

        bool isnot = (t == 1);
        const float *W2g, *b1g, *b2g;
        if (isnot) {
            stage_w_vec(sW1, g_Wnf1t, 1, 32, tid, 256);
            W2g = g_Wnf2t; b1g = bnf1; b2g = bnf2;
        } else {
            int fi = (t == 0) ? 0 : (t == 2) ? 1 : (t == 3) ? 2 : 3;
            stage_w_f1(sW1, g_Wf1t + fi * 32768, tid, 256);
            W2g = g_Wf2t + fi * 16384;
            b1g = bf1 + fi * 128;
            b2g = bf2 + fi * 128;
        }
        stage_w_vec(sW2, W2g, 1, 32, tid, 256);

        float4 xa[G], xb[G];
        int dr[G];
        {
            int nb = we - ws;
#pragma unroll
            for (int g = 0; g < G; g++) {
                xa[g] = make_float4(0.f, 0.f, 0.f, 0.f);
                xb[g] = xa[g];
                dr[g] = 0;
                if (g < nb) {
                    int sn = g_esrc[ws + g];
                    dr[g] = g_edst[ws + g];
                    if (isnot) {
                        xa[g] = ((const float4*)(hf + sn * 128))[lane];
                    } else {
                        xa[g] = ((const float4*)(hs + sn * 128))[lane];
                        xb[g] = ((const float4*)(hf + sn * 128))[lane];
                    }
                }
            }
        }
        float4 b1v = ((const float4*)b1g)[lane];
        float4 b2v = ((const float4*)b2g)[lane];
        __syncthreads();

        for (int base = ws; base < we; base += G) {
            int ne = min(G, we - base);
            int dc[G];
#pragma unroll
            for (int g = 0; g < G; g++) {
                ((float4*)(myX + g * 128))[lane] = xa[g];
                dc[g] = dr[g];
            }
            __syncwarp();
            int nb2 = we - (base + G);
            if (nb2 > 0) {
#pragma unroll
                for (int g = 0; g < G; g++) {
                    xa[g] = make_float4(0.f, 0.f, 0.f, 0.f);
                    if (g < nb2) {
                        int sn = g_esrc[base + G + g];
                        xa[g] = ((const float4*)((isnot ? hf : hs) + sn * 128))[lane];
                    }
                }
            }
            unsigned long long a1[G][4];
            gemm_p<G, 4, 32, 32, true>(sW1, myX, lane, a1);
            __syncwarp();
            if (!isnot) {
#pragma unroll
                for (int g = 0; g < G; g++)
                    ((float4*)(myX + g * 128))[lane] = xb[g];
                __syncwarp();
                if (nb2 > 0) {
#pragma unroll
                    for (int g = 0; g < G; g++) {
                        xb[g] = make_float4(0.f, 0.f, 0.f, 0.f);
                        if (g < nb2) {
                            int sn = g_esrc[base + G + g];
                            xb[g] = ((const float4*)(hf + sn * 128))[lane];
                        }
                    }
                }
                gemm_p<G, 4, 32, 32, false>(sW1 + 16384, myX, lane, a1);
                __syncwarp();
            }
            if (nb2 > 0) {
#pragma unroll
                for (int g = 0; g < G; g++)
                    dr[g] = (g < nb2) ? g_edst[base + G + g] : 0;
            }
#pragma unroll
            for (int g = 0; g < G; g++) {
                float4 y = make_float4(fmaxf(unpack_sum(a1[g][0]) + b1v.x, 0.f),
                                       fmaxf(unpack_sum(a1[g][1]) + b1v.y, 0.f),
                                       fmaxf(unpack_sum(a1[g][2]) + b1v.z, 0.f),
                                       fmaxf(unpack_sum(a1[g][3]) + b1v.w, 0.f));
                ((float4*)(myX + g * 128))[lane] = y;
            }
            __syncwarp();
            unsigned long long a2[G][4];
            gemm_p<G, 4, 32, 32, true>(sW2, myX, lane, a2);
#pragma unroll
            for (int g = 0; g < G; g++) {
                if (g < ne) {
                    float4 v = make_float4(unpack_sum(a2[g][0]) + b2v.x,
                                           unpack_sum(a2[g][1]) + b2v.y,
                                           unpack_sum(a2[g][2]) + b2v.z,
                                           unpack_sum(a2[g][3]) + b2v.w);
                    atomicAdd((float4*)&g_aggf[dc[g] * 128 + lane * 4], v);
                }
            }
            __syncwarp();
        }
    }
}

// ---------------- GRU (h == 0), fused s/f ----------------
#define GR_NW 8
#define GR_G 4
__global__ void __launch_bounds__(256, 1)
k_gru(const float* __restrict__ Gs_bih, const float* __restrict__ Gs_bhh,
      const float* __restrict__ Gf_bih, const float* __restrict__ Gf_bhh,
      float* __restrict__ hs, float* __restrict__ hf, int level) {
    extern __shared__ float sm[];
    float* sW = sm;
    float* sX = sm + 49152;

    int t = blockIdx.y % 5;
    int isF = blockIdx.y / 5;
    int b = (level - 1) * 5 + t;
    int nS = g_noff[b], cnt = g_noff[b + 1] - nS;

    const float* agg = isF ? g_aggf : g_aggs;
    float* hout = isF ? hf : hs;
    const float* wgp = (isF ? g_Gfwih_t : g_Gswih_t) + t * 49152;
    const float* bih = (isF ? Gf_bih : Gs_bih) + t * 384;
    const float* bhh = (isF ? Gf_bhh : Gs_bhh) + t * 384;

    int w = threadIdx.x >> 5, lane = threadIdx.x & 31;
    int nw = gridDim.x * GR_NW;
    int wgi = blockIdx.x * GR_NW + w;
    int ws = nS + (int)(((long long)cnt * wgi) / nw);
    int we = nS + (int)(((long long)cnt * (wgi + 1)) / nw);
    float* myX = sX + w * GR_G * 128;

    float4 xr[GR_G];
    int nr[GR_G];
    {
        int nb = we - ws;
#pragma unroll
        for (int g = 0; g < GR_G; g++) {
            xr[g] = make_float4(0.f, 0.f, 0.f, 0.f);
            nr[g] = 0;
            if (g < nb) {
                nr[g] = g_nodes[ws + g];
                xr[g] = ((const float4*)(agg + nr[g] * 128))[lane];
            }
        }
    }
    stage_w_vec(sW, wgp, 3, 32, threadIdx.x, 256);
    float4 bRi = ((const float4*)bih)[lane];
    float4 bRh = ((const float4*)bhh)[lane];
    float4 bZi = ((const float4*)(bih + 128))[lane];
    float4 bZh = ((const float4*)(bhh + 128))[lane];
    float4 bNi = ((const float4*)(bih + 256))[lane];
    float4 bNh = ((const float4*)(bhh + 256))[lane];
    float bR[4] = {bRi.x + bRh.x, bRi.y + bRh.y, bRi.z + bRh.z, bRi.w + bRh.w};
    float bZ[4] = {bZi.x + bZh.x, bZi.y + bZh.y, bZi.z + bZh.z, bZi.w + bZh.w};
    float bNiA[4] = {bNi.x, bNi.y, bNi.z, bNi.w};
    float bNhA[4] = {bNh.x, bNh.y, bNh.z, bNh.w};
    __syncthreads();

    for (int base = ws; base < we; base += GR_G) {
        int nn = min(GR_G, we - base);
        int nc[GR_G];
#pragma unroll
        for (int g = 0; g < GR_G; g++) {
            ((float4*)(myX + g * 128))[lane] = xr[g];
            nc[g] = nr[g];
        }
        __syncwarp();
        if (base + GR_G < we) {
            int nb = we - (base + GR_G);
#pragma unroll
            for (int g = 0; g < GR_G; g++) {
                xr[g] = make_float4(0.f, 0.f, 0.f, 0.f);
                nr[g] = 0;
                if (g < nb) {
                    nr[g] = g_nodes[base + GR_G + g];
                    xr[g] = ((const float4*)(agg + nr[g] * 128))[lane];
                }
            }
        }
        unsigned long long acc[GR_G][12];
        gemm_p<GR_G, 12, 32, 32, true>(sW, myX, lane, acc);
#pragma unroll
        for (int g = 0; g < GR_G; g++) {
            if (g < nn) {
                float o[4];
#pragma unroll
                for (int oi = 0; oi < 4; oi++) {
                    float r = sigmoidf_(unpack_sum(acc[g][oi]) + bR[oi]);
                    float z = sigmoidf_(unpack_sum(acc[g][oi + 4]) + bZ[oi]);
                    float n = tanhf(unpack_sum(acc[g][oi + 8]) + bNiA[oi] + r * bNhA[oi]);
                    o[oi] = (1.f - z) * n;
                }
                ((float4*)(hout + nc[g] * 128))[lane] = make_float4(o[0], o[1], o[2], o[3]);
            }
        }
        __syncwarp();
    }
}

// ---------------- host launch ----------------
extern "C" void kernel_launch(void* const* d_in, const int* in_sizes, int n_in,
                              void* d_out, int out_size) {
    const float* hs_init = (const float*)d_in[0];
    const float* Ws1 = (const float*)d_in[1];
    const float* bs1 = (const float*)d_in[2];
    const float* Ws2 = (const float*)d_in[3];
    const float* bs2 = (const float*)d_in[4];
    const float* Wf1 = (const float*)d_in[5];
    const float* bf1 = (const float*)d_in[6];
    const float* Wf2 = (const float*)d_in[7];
    const float* bf2 = (const float*)d_in[8];
    const float* Wnf1 = (const float*)d_in[9];
    const float* bnf1 = (const float*)d_in[10];
    const float* Wnf2 = (const float*)d_in[11];
    const float* bnf2 = (const float*)d_in[12];
    const float* Gs_wih = (const float*)d_in[13];
    const float* Gs_bih = (const float*)d_in[15];
    const float* Gs_bhh = (const float*)d_in[16];
    const float* Gf_wih = (const float*)d_in[17];
    const float* Gf_bih = (const float*)d_in[19];
    const float* Gf_bhh = (const float*)d_in[20];
    const int* edge_index = (const int*)d_in[21];
    const int* gate = (const int*)d_in[22];
    const int* flev = (const int*)d_in[23];

    float* hs = (float*)d_out;
    float* hf = hs + NN * DD;

    cudaFuncSetAttribute(k_edges, cudaFuncAttributeMaxDynamicSharedMemorySize, E_SMEM);
    cudaFuncSetAttribute(k_gru, cudaFuncAttributeMaxDynamicSharedMemorySize, 212992);

    k_init<<<1024, 256>>>(hs_init, gate, hs, hf, Ws1, Ws2, Wf1, Wf2, Wnf1, Wnf2,
                          Gs_wih, Gf_wih, edge_index, flev);
    k_scan<<<1, 1>>>();
    k_scatter<<<(EE + 255) / 256, 256>>>(edge_index, gate, flev);

    for (int level = 1; level < 5; level++) {
        k_edges<<<E_GRID, 256, E_SMEM>>>(hs, hf, bs1, bs2, bf1, bf2, bnf1, bnf2, level);
        k_gru<<<dim3(14, 10), 256, 212992>>>(Gs_bih, Gs_bhh, Gf_bih, Gf_bhh, hs, hf, level);
    }
}